// round 15
// baseline (speedup 1.0000x reference)
#include <cuda_runtime.h>
#include <cuda_fp16.h>

#define NN 50000
#define NE 800000
#define NB 196              // cdiv(NN,256)

// Scratch (device globals; referenced only from device code)
__device__ float   g_dis[NN];
__device__ int     g_deg[NN];
__device__ int     g_scan[NN];
__device__ int     g_bsum[256];
__device__ int     g_rowptr[NN + 1];
__device__ int     g_cur[NN];
__device__ float2  g_csw[NE];           // CSR (src-as-float-bits, weight) pairs
__device__ __half2 g_t16[NN * 64];      // linear-transform output (fp16)
__device__ __half2 g_h16[NN * 64];      // post-activation features (fp16)
__device__ __half  g_W1h[128 * 128];
__device__ __half  g_Whh[128 * 128];
__device__ __half  g_W2h[128 * 64];

static inline int cdiv(int a, int b) { return (a + b - 1) / b; }

// ---------------------------------------------------------------- weight fp16 pre-convert
__global__ void k_wconv(const float* __restrict__ W1, const float* __restrict__ Wh,
                        const float* __restrict__ W2)
{
    int i = blockIdx.x * blockDim.x + threadIdx.x;
    g_W1h[i] = __float2half_rn(W1[i]);
    g_Whh[i] = __float2half_rn(Wh[i]);
    if (i < 128 * 64) g_W2h[i] = __float2half_rn(W2[i]);
}

// ---------------------------------------------------------------- degree
__global__ void k_deg_init() {
    int i = blockIdx.x * blockDim.x + threadIdx.x;
    if (i < NN) g_deg[i] = 0;
}

__global__ void k_deg_count(const int* __restrict__ ei) {
    int e = blockIdx.x * blockDim.x + threadIdx.x;
    if (e < NE) atomicAdd(&g_deg[ei[NE + e]], 1);
}

// ---------------------------------------------------------------- scan
__global__ void k_scan1() {
    __shared__ int s[256];
    int i = blockIdx.x * 256 + threadIdx.x;
    int v = (i < NN) ? g_deg[i] : 0;
    if (i < NN) g_dis[i] = rsqrtf(1.0f + (float)v);
    s[threadIdx.x] = v;
    __syncthreads();
#pragma unroll
    for (int off = 1; off < 256; off <<= 1) {
        int t = (threadIdx.x >= off) ? s[threadIdx.x - off] : 0;
        __syncthreads();
        s[threadIdx.x] += t;
        __syncthreads();
    }
    if (i < NN) g_scan[i] = s[threadIdx.x];
    if (threadIdx.x == 255) g_bsum[blockIdx.x] = s[255];
}

__global__ void k_scan3() {
    __shared__ int s[256];
    int v = (threadIdx.x < blockIdx.x) ? g_bsum[threadIdx.x] : 0;
    s[threadIdx.x] = v;
    __syncthreads();
#pragma unroll
    for (int off = 128; off; off >>= 1) {
        if (threadIdx.x < off) s[threadIdx.x] += s[threadIdx.x + off];
        __syncthreads();
    }
    int boff = s[0];
    int i = blockIdx.x * 256 + threadIdx.x;
    if (i < NN) {
        int rp = g_scan[i] - g_deg[i] + boff;
        g_rowptr[i] = rp;
        g_cur[i] = rp;
    }
    if (i == 0) g_rowptr[NN] = NE;
}

// ---------------------------------------------------------------- CSR scatter
__global__ void k_scatter(const int* __restrict__ ei) {
    int e = blockIdx.x * blockDim.x + threadIdx.x;
    if (e >= NE) return;
    int s = ei[e];
    int d = ei[NE + e];
    int pos = atomicAdd(&g_cur[d], 1);
    g_csw[pos] = make_float2(__int_as_float(s), g_dis[s] * g_dis[d]);
}

// ---------------------------------------------------------------- fp16 MMA
__device__ __forceinline__ void mma_f16(float* d, const unsigned* a, const unsigned* b) {
    asm("mma.sync.aligned.m16n8k16.row.col.f32.f16.f16.f32 "
        "{%0,%1,%2,%3}, {%4,%5,%6,%7}, {%8,%9}, {%0,%1,%2,%3};"
        : "+f"(d[0]), "+f"(d[1]), "+f"(d[2]), "+f"(d[3])
        : "r"(a[0]), "r"(a[1]), "r"(a[2]), "r"(a[3]), "r"(b[0]), "r"(b[1]));
}

#define ASTH 24   // smem row stride (halves)

// ---------------------------------------------------------------- fp16 GEMM (double-buffered)
// g_t16[M,BN] = fp16( A[M,128] @ B[128,BN] ), fp32 accumulate.
// BM=128, BK=16, 8 warps (4m x 2n), warp tile 32 x BN/2, mma m16n8k16.
// A: fp32 global (layer 1) or g_h16. B: pre-converted fp16 (wsel).
template <int BN>
__global__ __launch_bounds__(256, 1) void gemm_f16(
    const float* __restrict__ Aparam, int M, int useH, int wsel)
{
    const __half* __restrict__ Bh = (wsel == 0) ? g_W1h : (wsel == 1) ? g_Whh : g_W2h;

    __shared__ __half As[2][128 * ASTH];   // [buf][m][k-chunk]
    __shared__ __half Bt[2][BN * ASTH];    // [buf][n][k-chunk] (transposed)

    const int tid = threadIdx.x;
    const int w = tid >> 5;
    const int lane = tid & 31;
    const int g = lane >> 2;        // 0..7
    const int tig = lane & 3;       // 0..3
    const int warp_m = (w & 3) * 32;
    const int warp_n = (w >> 2) * (BN / 2);
    const int m0 = blockIdx.y * 128;

    constexpr int NT = BN / 16;
    constexpr int HLD = (16 * BN) / 256;

    // chunk loader: loads A/B k-chunk c into buffer buf
    auto load_chunk = [&](int c, int buf) {
        int k0 = c * 16;
        if (useH) {
            int row = tid >> 1;
            int part = tid & 1;
            uint4 v = make_uint4(0, 0, 0, 0);
            if (m0 + row < M)
                v = *(const uint4*)(g_h16 + (long long)(m0 + row) * 64 + (k0 >> 1) + part * 4);
            *(uint4*)&As[buf][row * ASTH + part * 8] = v;
        } else {
            __half2* As2 = (__half2*)As[buf];
#pragma unroll
            for (int i = 0; i < 2; i++) {
                int idx = tid * 2 + i;
                int row = idx >> 2;
                int kc = (idx & 3) * 4;
                float4 av = make_float4(0.f, 0.f, 0.f, 0.f);
                if (m0 + row < M)
                    av = *(const float4*)(Aparam + (long long)(m0 + row) * 128 + k0 + kc);
                As2[(row * ASTH + kc) >> 1] = __floats2half2_rn(av.x, av.y);
                As2[(row * ASTH + kc + 2) >> 1] = __floats2half2_rn(av.z, av.w);
            }
        }
        {
            int krow = tid / (BN / HLD);
            int n0 = (tid % (BN / HLD)) * HLD;
            const __half* src = Bh + (long long)(k0 + krow) * BN + n0;
#pragma unroll
            for (int i = 0; i < HLD; i++)
                Bt[buf][(n0 + i) * ASTH + krow] = src[i];
        }
    };

    float acc[2][NT][4];
#pragma unroll
    for (int i = 0; i < 2; i++)
#pragma unroll
        for (int j = 0; j < NT; j++)
#pragma unroll
            for (int c = 0; c < 4; c++) acc[i][j][c] = 0.f;

    load_chunk(0, 0);
    __syncthreads();

#pragma unroll 1
    for (int c = 0; c < 8; c++) {
        int buf = c & 1;
        if (c < 7) load_chunk(c + 1, buf ^ 1);   // overlap with mma below

        __half2* As2 = (__half2*)As[buf];
        __half2* Bt2 = (__half2*)Bt[buf];

        unsigned a[2][4];
#pragma unroll
        for (int mt = 0; mt < 2; mt++) {
            int r0 = warp_m + mt * 16 + g;
            a[mt][0] = *(unsigned*)&As2[r0 * (ASTH / 2) + tig];
            a[mt][1] = *(unsigned*)&As2[(r0 + 8) * (ASTH / 2) + tig];
            a[mt][2] = *(unsigned*)&As2[r0 * (ASTH / 2) + tig + 4];
            a[mt][3] = *(unsigned*)&As2[(r0 + 8) * (ASTH / 2) + tig + 4];
        }
#pragma unroll
        for (int nt = 0; nt < NT; nt++) {
            int col = warp_n + nt * 8 + g;
            unsigned b[2];
            b[0] = *(unsigned*)&Bt2[col * (ASTH / 2) + tig];
            b[1] = *(unsigned*)&Bt2[col * (ASTH / 2) + tig + 4];
#pragma unroll
            for (int mt = 0; mt < 2; mt++)
                mma_f16(acc[mt][nt], a[mt], b);
        }
        __syncthreads();
    }

#pragma unroll
    for (int mt = 0; mt < 2; mt++) {
#pragma unroll
        for (int half = 0; half < 2; half++) {
            int r = m0 + warp_m + mt * 16 + g + half * 8;
            if (r < M) {
#pragma unroll
                for (int nt = 0; nt < NT; nt++) {
                    int c = warp_n + nt * 8 + tig * 2;
                    float2 v = half ? make_float2(acc[mt][nt][2], acc[mt][nt][3])
                                    : make_float2(acc[mt][nt][0], acc[mt][nt][1]);
                    g_t16[(long long)r * (BN / 2) + (c >> 1)] = __floats2half2_rn(v.x, v.y);
                }
            }
        }
    }
}

// ---------------------------------------------------------------- CSR aggregation (F=128)
// 128 threads = 2 nodes/block, 64 threads/node, 2 features/thread, unroll 8.
__global__ __launch_bounds__(128) void k_agg128(const float* __restrict__ bias)
{
    const int node = blockIdx.x * 2 + (threadIdx.x >> 6);
    const int tid  = threadIdx.x & 63;
    if (node >= NN) return;
    const int beg = g_rowptr[node];
    const int end = g_rowptr[node + 1];
    const float ds = g_dis[node];

    float2 self = __half22float2(g_t16[(long long)node * 64 + tid]);
    float ax = ds * ds * self.x;
    float ay = ds * ds * self.y;

    int j = beg;
    for (; j + 8 <= end; j += 8) {
        float2 e[8];
#pragma unroll
        for (int q = 0; q < 8; q++) e[q] = g_csw[j + q];
        float2 v[8];
#pragma unroll
        for (int q = 0; q < 8; q++)
            v[q] = __half22float2(g_t16[(long long)__float_as_int(e[q].x) * 64 + tid]);
#pragma unroll
        for (int q = 0; q < 8; q++) {
            ax += e[q].y * v[q].x;
            ay += e[q].y * v[q].y;
        }
    }
    for (; j < end; j++) {
        float2 e = g_csw[j];
        float2 v = __half22float2(g_t16[(long long)__float_as_int(e.x) * 64 + tid]);
        ax += e.y * v.x;
        ay += e.y * v.y;
    }

    float2 bb = *(const float2*)&bias[tid * 2];
    g_h16[(long long)node * 64 + tid] =
        __floats2half2_rn(fmaxf(ax + bb.x, 0.f), fmaxf(ay + bb.y, 0.f));
}

// ---------------------------------------------------------------- fused layer-3 agg + readout (F=64)
// 256 threads = 8 nodes/block, warp per node, 2 features/thread, unroll 8.
__global__ __launch_bounds__(256) void k_final64(
    const float* __restrict__ b2,
    const float* __restrict__ Wout,
    const float* __restrict__ bout,
    float* __restrict__ out)
{
    const int node = blockIdx.x * 8 + (threadIdx.x >> 5);
    const int tid  = threadIdx.x & 31;
    if (node >= NN) return;
    const int beg = g_rowptr[node];
    const int end = g_rowptr[node + 1];
    const float ds = g_dis[node];

    float2 self = __half22float2(g_t16[(long long)node * 32 + tid]);
    float ax = ds * ds * self.x;
    float ay = ds * ds * self.y;

    int j = beg;
    for (; j + 8 <= end; j += 8) {
        float2 e[8];
#pragma unroll
        for (int q = 0; q < 8; q++) e[q] = g_csw[j + q];
        float2 v[8];
#pragma unroll
        for (int q = 0; q < 8; q++)
            v[q] = __half22float2(g_t16[(long long)__float_as_int(e[q].x) * 32 + tid]);
#pragma unroll
        for (int q = 0; q < 8; q++) {
            ax += e[q].y * v[q].x;
            ay += e[q].y * v[q].y;
        }
    }
    for (; j < end; j++) {
        float2 e = g_csw[j];
        float2 v = __half22float2(g_t16[(long long)__float_as_int(e.x) * 32 + tid]);
        ax += e.y * v.x;
        ay += e.y * v.y;
    }

    float2 bb = *(const float2*)&b2[tid * 2];
    float vx = ax + bb.x;
    float vy = ay + bb.y;
    *(float2*)&out[NN + (long long)node * 64 + tid * 2] = make_float2(vx, vy);

    float2 ww = *(const float2*)&Wout[tid * 2];
    float p = vx * ww.x + vy * ww.y;
#pragma unroll
    for (int o = 16; o; o >>= 1) p += __shfl_down_sync(0xFFFFFFFFu, p, o);
    if (tid == 0) out[node] = p + bout[0];
}

// ---------------------------------------------------------------- launcher
extern "C" void kernel_launch(void* const* d_in, const int* in_sizes, int n_in,
                              void* d_out, int out_size)
{
    const float* x    = (const float*)d_in[0];
    const int*   ei   = (const int*)d_in[1];     // int32 (JAX x64 disabled)
    const float* W1   = (const float*)d_in[2];
    const float* b1   = (const float*)d_in[3];
    const float* Wh   = (const float*)d_in[4];
    const float* bh   = (const float*)d_in[5];
    const float* W2   = (const float*)d_in[6];
    const float* b2   = (const float*)d_in[7];
    const float* Wout = (const float*)d_in[8];
    const float* bout = (const float*)d_in[9];
    float*       out  = (float*)d_out;

    // Fork: CSR build runs concurrently with weight convert + layer-1 GEMM.
    cudaStream_t s2;
    cudaEvent_t ev_fork, ev_join;
    cudaStreamCreate(&s2);
    cudaEventCreate(&ev_fork);
    cudaEventCreate(&ev_join);

    cudaEventRecord(ev_fork, 0);
    cudaStreamWaitEvent(s2, ev_fork, 0);

    // ---- branch A (s2): normalization + CSR build
    k_deg_init<<<cdiv(NN, 256), 256, 0, s2>>>();
    k_deg_count<<<cdiv(NE, 256), 256, 0, s2>>>(ei);
    k_scan1<<<NB, 256, 0, s2>>>();
    k_scan3<<<NB, 256, 0, s2>>>();
    k_scatter<<<cdiv(NE, 256), 256, 0, s2>>>(ei);
    cudaEventRecord(ev_join, s2);

    // ---- branch B (default stream): weight convert + layer-1 GEMM
    k_wconv<<<64, 256>>>(W1, Wh, W2);
    dim3 gt(1, cdiv(NN, 128));
    gemm_f16<128><<<gt, 256>>>(x, NN, 0, 0);

    // join
    cudaStreamWaitEvent(0, ev_join, 0);

    // layer 1 aggregation
    k_agg128<<<cdiv(NN, 2), 128>>>(b1);
    // layer 2
    gemm_f16<128><<<gt, 256>>>(nullptr, NN, 1, 1);
    k_agg128<<<cdiv(NN, 2), 128>>>(bh);
    // layer 3 (128 -> 64) + fused readout
    gemm_f16<64><<<gt, 256>>>(nullptr, NN, 1, 2);
    k_final64<<<cdiv(NN, 8), 256>>>(b2, Wout, bout, out);
}

// round 16
// speedup vs baseline: 1.0088x; 1.0088x over previous
#include <cuda_runtime.h>
#include <cuda_fp16.h>

#define NN 50000
#define NE 800000
#define NB 196              // cdiv(NN,256)

// Scratch (device globals; referenced only from device code)
__device__ float   g_dis[NN];
__device__ int     g_deg[NN];       // zeroed at end of each replay (by k_scatter)
__device__ int     g_ticket;        // zeroed at end of each replay (by k_scatter)
__device__ int     g_rowbeg[NN];
__device__ int     g_rowend[NN];
__device__ int     g_cur[NN];
__device__ float2  g_csw[NE];       // CSR (src-as-float-bits, weight) pairs
__device__ __half2 g_t16[NN * 64];  // linear-transform output (fp16)
__device__ __half2 g_h16[NN * 64];  // post-activation features (fp16)
__device__ __half  g_W1h[128 * 128];
__device__ __half  g_Whh[128 * 128];
__device__ __half  g_W2h[128 * 64];

static inline int cdiv(int a, int b) { return (a + b - 1) / b; }

// ---------------------------------------------------------------- weight fp16 pre-convert
__global__ void k_wconv1(const float* __restrict__ W1) {
    int i = blockIdx.x * blockDim.x + threadIdx.x;
    g_W1h[i] = __float2half_rn(W1[i]);
}

__global__ void k_wconv23(const float* __restrict__ Wh, const float* __restrict__ W2) {
    int i = blockIdx.x * blockDim.x + threadIdx.x;
    g_Whh[i] = __float2half_rn(Wh[i]);
    if (i < 128 * 64) g_W2h[i] = __float2half_rn(W2[i]);
}

// ---------------------------------------------------------------- degree count (g_deg pre-zeroed)
__global__ void k_deg_count(const int* __restrict__ ei) {
    int e = blockIdx.x * blockDim.x + threadIdx.x;
    if (e < NE) atomicAdd(&g_deg[ei[NE + e]], 1);
}

// ---------------------------------------------------------------- single-kernel ticket scan
// Per-block local inclusive scan + atomic ticket for block offset.
// Block order is arbitrary -> rowbeg values vary between replays, but ranges
// are always disjoint and correctly sized (beg & end written by same block).
__global__ void k_scan() {
    __shared__ int s[256];
    __shared__ int boff;
    int i = blockIdx.x * 256 + threadIdx.x;
    int v = (i < NN) ? g_deg[i] : 0;
    if (i < NN) g_dis[i] = rsqrtf(1.0f + (float)v);
    s[threadIdx.x] = v;
    __syncthreads();
#pragma unroll
    for (int off = 1; off < 256; off <<= 1) {
        int t = (threadIdx.x >= off) ? s[threadIdx.x - off] : 0;
        __syncthreads();
        s[threadIdx.x] += t;
        __syncthreads();
    }
    if (threadIdx.x == 255) boff = atomicAdd(&g_ticket, s[255]);
    __syncthreads();
    if (i < NN) {
        int beg = boff + s[threadIdx.x] - v;
        g_rowbeg[i] = beg;
        g_rowend[i] = beg + v;
        g_cur[i]    = beg;
    }
}

// ---------------------------------------------------------------- CSR scatter (+ re-zero for next replay)
__global__ void k_scatter(const int* __restrict__ ei) {
    int e = blockIdx.x * blockDim.x + threadIdx.x;
    if (e < NN) g_deg[e] = 0;          // degrees are dead now; prep next replay
    if (e == 0) g_ticket = 0;
    if (e >= NE) return;
    int s = ei[e];
    int d = ei[NE + e];
    int pos = atomicAdd(&g_cur[d], 1);
    g_csw[pos] = make_float2(__int_as_float(s), g_dis[s] * g_dis[d]);
}

// ---------------------------------------------------------------- fp16 MMA
__device__ __forceinline__ void mma_f16(float* d, const unsigned* a, const unsigned* b) {
    asm("mma.sync.aligned.m16n8k16.row.col.f32.f16.f16.f32 "
        "{%0,%1,%2,%3}, {%4,%5,%6,%7}, {%8,%9}, {%0,%1,%2,%3};"
        : "+f"(d[0]), "+f"(d[1]), "+f"(d[2]), "+f"(d[3])
        : "r"(a[0]), "r"(a[1]), "r"(a[2]), "r"(a[3]), "r"(b[0]), "r"(b[1]));
}

#define ASTH 24   // smem row stride (halves)

// ---------------------------------------------------------------- fp16 GEMM (double-buffered)
template <int BN>
__global__ __launch_bounds__(256, 1) void gemm_f16(
    const float* __restrict__ Aparam, int M, int useH, int wsel)
{
    const __half* __restrict__ Bh = (wsel == 0) ? g_W1h : (wsel == 1) ? g_Whh : g_W2h;

    __shared__ __half As[2][128 * ASTH];
    __shared__ __half Bt[2][BN * ASTH];

    const int tid = threadIdx.x;
    const int w = tid >> 5;
    const int lane = tid & 31;
    const int g = lane >> 2;
    const int tig = lane & 3;
    const int warp_m = (w & 3) * 32;
    const int warp_n = (w >> 2) * (BN / 2);
    const int m0 = blockIdx.y * 128;

    constexpr int NT = BN / 16;
    constexpr int HLD = (16 * BN) / 256;

    auto load_chunk = [&](int c, int buf) {
        int k0 = c * 16;
        if (useH) {
            int row = tid >> 1;
            int part = tid & 1;
            uint4 v = make_uint4(0, 0, 0, 0);
            if (m0 + row < M)
                v = *(const uint4*)(g_h16 + (long long)(m0 + row) * 64 + (k0 >> 1) + part * 4);
            *(uint4*)&As[buf][row * ASTH + part * 8] = v;
        } else {
            __half2* As2 = (__half2*)As[buf];
#pragma unroll
            for (int i = 0; i < 2; i++) {
                int idx = tid * 2 + i;
                int row = idx >> 2;
                int kc = (idx & 3) * 4;
                float4 av = make_float4(0.f, 0.f, 0.f, 0.f);
                if (m0 + row < M)
                    av = *(const float4*)(Aparam + (long long)(m0 + row) * 128 + k0 + kc);
                As2[(row * ASTH + kc) >> 1] = __floats2half2_rn(av.x, av.y);
                As2[(row * ASTH + kc + 2) >> 1] = __floats2half2_rn(av.z, av.w);
            }
        }
        {
            int krow = tid / (BN / HLD);
            int n0 = (tid % (BN / HLD)) * HLD;
            const __half* src = Bh + (long long)(k0 + krow) * BN + n0;
#pragma unroll
            for (int i = 0; i < HLD; i++)
                Bt[buf][(n0 + i) * ASTH + krow] = src[i];
        }
    };

    float acc[2][NT][4];
#pragma unroll
    for (int i = 0; i < 2; i++)
#pragma unroll
        for (int j = 0; j < NT; j++)
#pragma unroll
            for (int c = 0; c < 4; c++) acc[i][j][c] = 0.f;

    load_chunk(0, 0);
    __syncthreads();

#pragma unroll 1
    for (int c = 0; c < 8; c++) {
        int buf = c & 1;
        if (c < 7) load_chunk(c + 1, buf ^ 1);

        __half2* As2 = (__half2*)As[buf];
        __half2* Bt2 = (__half2*)Bt[buf];

        unsigned a[2][4];
#pragma unroll
        for (int mt = 0; mt < 2; mt++) {
            int r0 = warp_m + mt * 16 + g;
            a[mt][0] = *(unsigned*)&As2[r0 * (ASTH / 2) + tig];
            a[mt][1] = *(unsigned*)&As2[(r0 + 8) * (ASTH / 2) + tig];
            a[mt][2] = *(unsigned*)&As2[r0 * (ASTH / 2) + tig + 4];
            a[mt][3] = *(unsigned*)&As2[(r0 + 8) * (ASTH / 2) + tig + 4];
        }
#pragma unroll
        for (int nt = 0; nt < NT; nt++) {
            int col = warp_n + nt * 8 + g;
            unsigned b[2];
            b[0] = *(unsigned*)&Bt2[col * (ASTH / 2) + tig];
            b[1] = *(unsigned*)&Bt2[col * (ASTH / 2) + tig + 4];
#pragma unroll
            for (int mt = 0; mt < 2; mt++)
                mma_f16(acc[mt][nt], a[mt], b);
        }
        __syncthreads();
    }

#pragma unroll
    for (int mt = 0; mt < 2; mt++) {
#pragma unroll
        for (int half = 0; half < 2; half++) {
            int r = m0 + warp_m + mt * 16 + g + half * 8;
            if (r < M) {
#pragma unroll
                for (int nt = 0; nt < NT; nt++) {
                    int c = warp_n + nt * 8 + tig * 2;
                    float2 v = half ? make_float2(acc[mt][nt][2], acc[mt][nt][3])
                                    : make_float2(acc[mt][nt][0], acc[mt][nt][1]);
                    g_t16[(long long)r * (BN / 2) + (c >> 1)] = __floats2half2_rn(v.x, v.y);
                }
            }
        }
    }
}

// ---------------------------------------------------------------- CSR aggregation (F=128)
__global__ __launch_bounds__(128) void k_agg128(const float* __restrict__ bias)
{
    const int node = blockIdx.x * 2 + (threadIdx.x >> 6);
    const int tid  = threadIdx.x & 63;
    if (node >= NN) return;
    const int beg = g_rowbeg[node];
    const int end = g_rowend[node];
    const float ds = g_dis[node];

    float2 self = __half22float2(g_t16[(long long)node * 64 + tid]);
    float ax = ds * ds * self.x;
    float ay = ds * ds * self.y;

    int j = beg;
    for (; j + 8 <= end; j += 8) {
        float2 e[8];
#pragma unroll
        for (int q = 0; q < 8; q++) e[q] = g_csw[j + q];
        float2 v[8];
#pragma unroll
        for (int q = 0; q < 8; q++)
            v[q] = __half22float2(g_t16[(long long)__float_as_int(e[q].x) * 64 + tid]);
#pragma unroll
        for (int q = 0; q < 8; q++) {
            ax += e[q].y * v[q].x;
            ay += e[q].y * v[q].y;
        }
    }
    for (; j < end; j++) {
        float2 e = g_csw[j];
        float2 v = __half22float2(g_t16[(long long)__float_as_int(e.x) * 64 + tid]);
        ax += e.y * v.x;
        ay += e.y * v.y;
    }

    float2 bb = *(const float2*)&bias[tid * 2];
    g_h16[(long long)node * 64 + tid] =
        __floats2half2_rn(fmaxf(ax + bb.x, 0.f), fmaxf(ay + bb.y, 0.f));
}

// ---------------------------------------------------------------- fused layer-3 agg + readout (F=64)
__global__ __launch_bounds__(256) void k_final64(
    const float* __restrict__ b2,
    const float* __restrict__ Wout,
    const float* __restrict__ bout,
    float* __restrict__ out)
{
    const int node = blockIdx.x * 8 + (threadIdx.x >> 5);
    const int tid  = threadIdx.x & 31;
    if (node >= NN) return;
    const int beg = g_rowbeg[node];
    const int end = g_rowend[node];
    const float ds = g_dis[node];

    float2 self = __half22float2(g_t16[(long long)node * 32 + tid]);
    float ax = ds * ds * self.x;
    float ay = ds * ds * self.y;

    int j = beg;
    for (; j + 8 <= end; j += 8) {
        float2 e[8];
#pragma unroll
        for (int q = 0; q < 8; q++) e[q] = g_csw[j + q];
        float2 v[8];
#pragma unroll
        for (int q = 0; q < 8; q++)
            v[q] = __half22float2(g_t16[(long long)__float_as_int(e[q].x) * 32 + tid]);
#pragma unroll
        for (int q = 0; q < 8; q++) {
            ax += e[q].y * v[q].x;
            ay += e[q].y * v[q].y;
        }
    }
    for (; j < end; j++) {
        float2 e = g_csw[j];
        float2 v = __half22float2(g_t16[(long long)__float_as_int(e.x) * 32 + tid]);
        ax += e.y * v.x;
        ay += e.y * v.y;
    }

    float2 bb = *(const float2*)&b2[tid * 2];
    float vx = ax + bb.x;
    float vy = ay + bb.y;
    *(float2*)&out[NN + (long long)node * 64 + tid * 2] = make_float2(vx, vy);

    float2 ww = *(const float2*)&Wout[tid * 2];
    float p = vx * ww.x + vy * ww.y;
#pragma unroll
    for (int o = 16; o; o >>= 1) p += __shfl_down_sync(0xFFFFFFFFu, p, o);
    if (tid == 0) out[node] = p + bout[0];
}

// ---------------------------------------------------------------- launcher
extern "C" void kernel_launch(void* const* d_in, const int* in_sizes, int n_in,
                              void* d_out, int out_size)
{
    const float* x    = (const float*)d_in[0];
    const int*   ei   = (const int*)d_in[1];     // int32 (JAX x64 disabled)
    const float* W1   = (const float*)d_in[2];
    const float* b1   = (const float*)d_in[3];
    const float* Wh   = (const float*)d_in[4];
    const float* bh   = (const float*)d_in[5];
    const float* W2   = (const float*)d_in[6];
    const float* b2   = (const float*)d_in[7];
    const float* Wout = (const float*)d_in[8];
    const float* bout = (const float*)d_in[9];
    float*       out  = (float*)d_out;

    // Fork: CSR build (s2) concurrent with W1 convert + layer-1 GEMM (s0).
    cudaStream_t s2;
    cudaEvent_t ev_fork, ev_join;
    cudaStreamCreate(&s2);
    cudaEventCreate(&ev_fork);
    cudaEventCreate(&ev_join);

    cudaEventRecord(ev_fork, 0);
    cudaStreamWaitEvent(s2, ev_fork, 0);

    // ---- branch A (s2): CSR build (3 launches) + Wh/W2 convert (hidden)
    k_deg_count<<<cdiv(NE, 256), 256, 0, s2>>>(ei);
    k_scan<<<NB, 256, 0, s2>>>();
    k_scatter<<<cdiv(NE, 256), 256, 0, s2>>>(ei);
    k_wconv23<<<64, 256, 0, s2>>>(Wh, W2);
    cudaEventRecord(ev_join, s2);

    // ---- branch B (s0): W1 convert + layer-1 GEMM
    k_wconv1<<<64, 256>>>(W1);
    dim3 gt(1, cdiv(NN, 128));
    gemm_f16<128><<<gt, 256>>>(x, NN, 0, 0);

    // join
    cudaStreamWaitEvent(0, ev_join, 0);

    // layer 1 aggregation
    k_agg128<<<cdiv(NN, 2), 128>>>(b1);
    // layer 2
    gemm_f16<128><<<gt, 256>>>(nullptr, NN, 1, 1);
    k_agg128<<<cdiv(NN, 2), 128>>>(bh);
    // layer 3 (128 -> 64) + fused readout
    gemm_f16<64><<<gt, 256>>>(nullptr, NN, 1, 2);
    k_final64<<<cdiv(NN, 8), 256>>>(b2, Wout, bout, out);
}